// round 1
// baseline (speedup 1.0000x reference)
#include <cuda_runtime.h>
#include <cuda_bf16.h>

// Problem constants (fixed shapes per reference setup_inputs)
#define HOPS    3
#define NTAB    4          // HOPS+1 embedding tables
#define VOCAB   50257
#define DIM     128
#define BATCH   32
#define M_SLOTS 512        // story slots
#define S_TOK   6          // tokens per story slot
#define T_TREE  128        // trees per example
#define L_TOK   64         // tokens per tree
#define SLOTS   (M_SLOTS + T_TREE)   // 640

// Scratch: per-table per-batch per-slot summed embeddings, and the hop state u.
// 4 * 32 * 640 * 128 floats = 41.94 MB
__device__ float g_M[(size_t)NTAB * BATCH * SLOTS * DIM];
__device__ float g_u[BATCH * DIM];

// ---------------------------------------------------------------------------
// Phase 1: gather-sum all 4 tables' slot memories.
// One warp per (table, batch, slot). Lane l owns dims [4l, 4l+4) as float4.
// ---------------------------------------------------------------------------
__global__ void __launch_bounds__(256) gather_kernel(
    const float* __restrict__ C,
    const int*   __restrict__ story,
    const int*   __restrict__ kb)
{
    // Zero the hop state u (block 0 only; hop kernels run after this kernel).
    if (blockIdx.x == 0) {
        for (int i = threadIdx.x; i < BATCH * DIM; i += blockDim.x)
            g_u[i] = 0.0f;
    }

    const int lane = threadIdx.x & 31;
    const int wg   = blockIdx.x * (blockDim.x >> 5) + (threadIdx.x >> 5);
    // wg = ((t * BATCH + b) * SLOTS + slot)
    const int t    = wg / (BATCH * SLOTS);
    const int rem  = wg % (BATCH * SLOTS);
    const int b    = rem / SLOTS;
    const int slot = rem % SLOTS;

    const float4* __restrict__ Ct =
        reinterpret_cast<const float4*>(C + (size_t)t * VOCAB * DIM);

    float4 acc = make_float4(0.f, 0.f, 0.f, 0.f);

    if (slot < M_SLOTS) {
        const int* toks = story + ((size_t)b * M_SLOTS + slot) * S_TOK;
        int tk[S_TOK];
        #pragma unroll
        for (int j = 0; j < S_TOK; ++j) tk[j] = toks[j];
        #pragma unroll
        for (int j = 0; j < S_TOK; ++j) {
            float4 v = Ct[(size_t)tk[j] * (DIM / 4) + lane];
            acc.x += v.x; acc.y += v.y; acc.z += v.z; acc.w += v.w;
        }
    } else {
        const int* toks = kb + ((size_t)b * T_TREE + (slot - M_SLOTS)) * L_TOK;
        float4 a0 = make_float4(0.f, 0.f, 0.f, 0.f);
        float4 a1 = a0, a2 = a0, a3 = a0;
        #pragma unroll 4
        for (int j = 0; j < L_TOK; j += 4) {
            int t0 = toks[j + 0], t1 = toks[j + 1];
            int t2 = toks[j + 2], t3 = toks[j + 3];
            float4 v0 = Ct[(size_t)t0 * (DIM / 4) + lane];
            float4 v1 = Ct[(size_t)t1 * (DIM / 4) + lane];
            float4 v2 = Ct[(size_t)t2 * (DIM / 4) + lane];
            float4 v3 = Ct[(size_t)t3 * (DIM / 4) + lane];
            a0.x += v0.x; a0.y += v0.y; a0.z += v0.z; a0.w += v0.w;
            a1.x += v1.x; a1.y += v1.y; a1.z += v1.z; a1.w += v1.w;
            a2.x += v2.x; a2.y += v2.y; a2.z += v2.z; a2.w += v2.w;
            a3.x += v3.x; a3.y += v3.y; a3.z += v3.z; a3.w += v3.w;
        }
        acc.x = (a0.x + a1.x) + (a2.x + a3.x);
        acc.y = (a0.y + a1.y) + (a2.y + a3.y);
        acc.z = (a0.z + a1.z) + (a2.z + a3.z);
        acc.w = (a0.w + a1.w) + (a2.w + a3.w);
    }

    float4* out = reinterpret_cast<float4*>(g_M) + (size_t)wg * (DIM / 4);
    out[lane] = acc;
}

// ---------------------------------------------------------------------------
// Phase 2: one hop. One block per batch element, 256 threads (8 warps).
//   scores[slot] = dot(M_key[b,slot,:], u[b,:])
//   prob = softmax(scores)  (over 640 slots)
//   u[b,:] += sum_slot prob[slot] * M_val[b,slot,:]
// ---------------------------------------------------------------------------
__global__ void __launch_bounds__(256) hop_kernel(int hop, float* __restrict__ out)
{
    const int b    = blockIdx.x;
    const int tid  = threadIdx.x;
    const int w    = tid >> 5;
    const int lane = tid & 31;

    __shared__ float  s_score[SLOTS];
    __shared__ float  s_red[16];
    __shared__ float4 s_part[8][32];

    // u[b] as float4 per lane (dims 4*lane .. 4*lane+3), same in all warps
    const float4* u4p = reinterpret_cast<const float4*>(g_u + b * DIM);
    const float4  u4  = u4p[lane];

    const float* Mk = g_M + ((size_t)(hop       * BATCH + b) * SLOTS) * DIM;
    const float* Mv = g_M + ((size_t)((hop + 1) * BATCH + b) * SLOTS) * DIM;

    // --- scores: warp per slot, strided ---
    for (int slot = w; slot < SLOTS; slot += 8) {
        const float4 v = reinterpret_cast<const float4*>(Mk + (size_t)slot * DIM)[lane];
        float p = v.x * u4.x + v.y * u4.y + v.z * u4.z + v.w * u4.w;
        #pragma unroll
        for (int o = 16; o; o >>= 1) p += __shfl_xor_sync(0xffffffffu, p, o);
        if (lane == 0) s_score[slot] = p;
    }
    __syncthreads();

    // --- softmax over 640 slots ---
    float m = -1e30f;
    for (int i = tid; i < SLOTS; i += 256) m = fmaxf(m, s_score[i]);
    #pragma unroll
    for (int o = 16; o; o >>= 1) m = fmaxf(m, __shfl_xor_sync(0xffffffffu, m, o));
    if (lane == 0) s_red[w] = m;
    __syncthreads();
    m = s_red[0];
    #pragma unroll
    for (int i = 1; i < 8; ++i) m = fmaxf(m, s_red[i]);

    float sum = 0.f;
    for (int i = tid; i < SLOTS; i += 256) {
        float e = __expf(s_score[i] - m);
        s_score[i] = e;          // unnormalized prob
        sum += e;
    }
    #pragma unroll
    for (int o = 16; o; o >>= 1) sum += __shfl_xor_sync(0xffffffffu, sum, o);
    if (lane == 0) s_red[8 + w] = sum;
    __syncthreads();
    sum = 0.f;
    #pragma unroll
    for (int i = 0; i < 8; ++i) sum += s_red[8 + i];
    const float inv = 1.0f / sum;

    // --- weighted value sum ---
    float4 o4 = make_float4(0.f, 0.f, 0.f, 0.f);
    for (int slot = w; slot < SLOTS; slot += 8) {
        const float  p = s_score[slot];
        const float4 v = reinterpret_cast<const float4*>(Mv + (size_t)slot * DIM)[lane];
        o4.x += p * v.x; o4.y += p * v.y; o4.z += p * v.z; o4.w += p * v.w;
    }
    s_part[w][lane] = o4;
    __syncthreads();

    if (tid < 32) {   // 32 lanes x float4 = all 128 dims
        float4 r = make_float4(0.f, 0.f, 0.f, 0.f);
        #pragma unroll
        for (int i = 0; i < 8; ++i) {
            float4 p = s_part[i][lane];
            r.x += p.x; r.y += p.y; r.z += p.z; r.w += p.w;
        }
        float4 un;
        un.x = u4.x + r.x * inv;
        un.y = u4.y + r.y * inv;
        un.z = u4.z + r.z * inv;
        un.w = u4.w + r.w * inv;
        reinterpret_cast<float4*>(g_u + b * DIM)[lane] = un;
        if (hop == HOPS - 1)
            reinterpret_cast<float4*>(out + b * DIM)[lane] = un;
    }
}

// ---------------------------------------------------------------------------
extern "C" void kernel_launch(void* const* d_in, const int* in_sizes, int n_in,
                              void* d_out, int out_size)
{
    const float* C     = (const float*)d_in[0];  // [4, 50257, 128]
    const int*   story = (const int*)  d_in[1];  // [32, 512, 6]
    const int*   kb    = (const int*)  d_in[2];  // [32, 128, 64]
    float*       out   = (float*)d_out;          // [32, 128]

    // Phase 1: 4*32*640 = 81920 warps -> 10240 blocks of 8 warps
    const int total_warps = NTAB * BATCH * SLOTS;
    gather_kernel<<<total_warps / 8, 256>>>(C, story, kb);

    // Phase 2: 3 sequential hops
    for (int hop = 0; hop < HOPS; ++hop)
        hop_kernel<<<BATCH, 256>>>(hop, out);
}

// round 2
// speedup vs baseline: 2.1246x; 2.1246x over previous
#include <cuda_runtime.h>
#include <cuda_bf16.h>

#define HOPS    3
#define NTAB    4
#define VOCAB   50257
#define DIM     128
#define BATCH   32
#define M_SLOTS 512
#define S_TOK   6
#define T_TREE  128
#define L_TOK   64
#define SLOTS   (M_SLOTS + T_TREE)   // 640

#define SPLITS   20                  // slot-splits per batch per hop
#define SLOTS_PB (SLOTS / SPLITS)    // 32 slots per block
#define REC      132                 // floats per partial record: m, s, pad, pad, o[128]

// Scratch (42 MB + 1 MB)
__device__ float g_M[(size_t)NTAB * BATCH * SLOTS * DIM];
__device__ __align__(16) float g_part[(size_t)HOPS * BATCH * SPLITS * REC];

__device__ __forceinline__ float warp_max(float v) {
    #pragma unroll
    for (int o = 16; o; o >>= 1) v = fmaxf(v, __shfl_xor_sync(0xffffffffu, v, o));
    return v;
}
__device__ __forceinline__ float warp_sum(float v) {
    #pragma unroll
    for (int o = 16; o; o >>= 1) v += __shfl_xor_sync(0xffffffffu, v, o);
    return v;
}

// ---------------------------------------------------------------------------
// Phase 1: gather-sum all 4 tables' slot memories. One warp per (table,b,slot).
// ---------------------------------------------------------------------------
__global__ void __launch_bounds__(256) gather_kernel(
    const float* __restrict__ C,
    const int*   __restrict__ story,
    const int*   __restrict__ kb)
{
    const int lane = threadIdx.x & 31;
    const int wg   = blockIdx.x * (blockDim.x >> 5) + (threadIdx.x >> 5);
    const int t    = wg / (BATCH * SLOTS);
    const int rem  = wg % (BATCH * SLOTS);
    const int b    = rem / SLOTS;
    const int slot = rem % SLOTS;

    const float4* __restrict__ Ct =
        reinterpret_cast<const float4*>(C + (size_t)t * VOCAB * DIM);

    float4 acc = make_float4(0.f, 0.f, 0.f, 0.f);

    if (slot < M_SLOTS) {
        const int* toks = story + ((size_t)b * M_SLOTS + slot) * S_TOK;
        int tk[S_TOK];
        #pragma unroll
        for (int j = 0; j < S_TOK; ++j) tk[j] = toks[j];
        #pragma unroll
        for (int j = 0; j < S_TOK; ++j) {
            float4 v = Ct[(size_t)tk[j] * (DIM / 4) + lane];
            acc.x += v.x; acc.y += v.y; acc.z += v.z; acc.w += v.w;
        }
    } else {
        const int* toks = kb + ((size_t)b * T_TREE + (slot - M_SLOTS)) * L_TOK;
        float4 a0 = make_float4(0.f, 0.f, 0.f, 0.f);
        float4 a1 = a0, a2 = a0, a3 = a0;
        #pragma unroll 4
        for (int j = 0; j < L_TOK; j += 4) {
            int t0 = toks[j + 0], t1 = toks[j + 1];
            int t2 = toks[j + 2], t3 = toks[j + 3];
            float4 v0 = Ct[(size_t)t0 * (DIM / 4) + lane];
            float4 v1 = Ct[(size_t)t1 * (DIM / 4) + lane];
            float4 v2 = Ct[(size_t)t2 * (DIM / 4) + lane];
            float4 v3 = Ct[(size_t)t3 * (DIM / 4) + lane];
            a0.x += v0.x; a0.y += v0.y; a0.z += v0.z; a0.w += v0.w;
            a1.x += v1.x; a1.y += v1.y; a1.z += v1.z; a1.w += v1.w;
            a2.x += v2.x; a2.y += v2.y; a2.z += v2.z; a2.w += v2.w;
            a3.x += v3.x; a3.y += v3.y; a3.z += v3.z; a3.w += v3.w;
        }
        acc.x = (a0.x + a1.x) + (a2.x + a3.x);
        acc.y = (a0.y + a1.y) + (a2.y + a3.y);
        acc.z = (a0.z + a1.z) + (a2.z + a3.z);
        acc.w = (a0.w + a1.w) + (a2.w + a3.w);
    }

    float4* out = reinterpret_cast<float4*>(g_M) + (size_t)wg * (DIM / 4);
    out[lane] = acc;
}

// ---------------------------------------------------------------------------
// Reconstruct u contribution of one previous hop j for batch b.
// Warp-collective; lane owns dims [4*lane, 4*lane+4). Returns o/s as float4.
// ---------------------------------------------------------------------------
__device__ __forceinline__ float4 combine_hop(int j, int b, int lane)
{
    const float* __restrict__ base =
        g_part + ((size_t)(j * BATCH + b)) * SPLITS * REC;

    float mi = (lane < SPLITS) ? base[lane * REC] : -1e30f;
    const float m = warp_max(mi);

    float s_acc = 0.f;
    float4 o4 = make_float4(0.f, 0.f, 0.f, 0.f);
    #pragma unroll
    for (int i = 0; i < SPLITS; ++i) {
        const float* rec = base + (size_t)i * REC;
        float e = __expf(rec[0] - m);
        s_acc += rec[1] * e;
        float4 oi = reinterpret_cast<const float4*>(rec + 4)[lane];
        o4.x += e * oi.x; o4.y += e * oi.y; o4.z += e * oi.z; o4.w += e * oi.w;
    }
    const float inv = 1.0f / s_acc;
    o4.x *= inv; o4.y *= inv; o4.z *= inv; o4.w *= inv;
    return o4;
}

// ---------------------------------------------------------------------------
// Phase 2: one hop, split over slots. Block = (b, split) handles 32 slots.
// Writes flash-style partial (m, s, o[128]) for later combination.
// ---------------------------------------------------------------------------
__global__ void __launch_bounds__(256) hop_kernel(int hop)
{
    const int b     = blockIdx.x / SPLITS;
    const int split = blockIdx.x % SPLITS;
    const int w     = threadIdx.x >> 5;
    const int lane  = threadIdx.x & 31;

    __shared__ float4 u_hs[2][32];
    __shared__ float  s_score[SLOTS_PB];
    __shared__ float4 s_part[8][32];
    __shared__ float  s_ms[2];

    // --- reconstruct u_hop from previous hops' partials (redundant per block) ---
    float4 u4 = make_float4(0.f, 0.f, 0.f, 0.f);
    if (hop > 0) {
        if (w < hop)
            u_hs[w][lane] = combine_hop(w, b, lane);
        __syncthreads();
        u4 = u_hs[0][lane];
        if (hop == 2) {
            float4 t = u_hs[1][lane];
            u4.x += t.x; u4.y += t.y; u4.z += t.z; u4.w += t.w;
        }
    }

    const float* __restrict__ Mk =
        g_M + ((size_t)(hop * BATCH + b) * SLOTS + split * SLOTS_PB) * DIM;
    const float* __restrict__ Mv =
        g_M + ((size_t)((hop + 1) * BATCH + b) * SLOTS + split * SLOTS_PB) * DIM;

    // --- scores: warp w handles local slots w, w+8, w+16, w+24 ---
    #pragma unroll
    for (int k = 0; k < SLOTS_PB / 8; ++k) {
        const int ls = w + k * 8;
        const float4 v = reinterpret_cast<const float4*>(Mk + (size_t)ls * DIM)[lane];
        float p = v.x * u4.x + v.y * u4.y + v.z * u4.z + v.w * u4.w;
        p = warp_sum(p);
        if (lane == 0) s_score[ls] = p;
    }
    __syncthreads();

    // --- local softmax over 32 scores (warp 0) ---
    if (w == 0) {
        float sc = s_score[lane];
        float m  = warp_max(sc);
        float e  = __expf(sc - m);
        float s  = warp_sum(e);
        s_score[lane] = e;                // unnormalized local prob
        if (lane == 0) { s_ms[0] = m; s_ms[1] = s; }
    }
    __syncthreads();

    // --- weighted value partial ---
    float4 o4 = make_float4(0.f, 0.f, 0.f, 0.f);
    #pragma unroll
    for (int k = 0; k < SLOTS_PB / 8; ++k) {
        const int ls = w + k * 8;
        const float  p = s_score[ls];
        const float4 v = reinterpret_cast<const float4*>(Mv + (size_t)ls * DIM)[lane];
        o4.x += p * v.x; o4.y += p * v.y; o4.z += p * v.z; o4.w += p * v.w;
    }
    s_part[w][lane] = o4;
    __syncthreads();

    if (w == 0) {
        float4 r = make_float4(0.f, 0.f, 0.f, 0.f);
        #pragma unroll
        for (int i = 0; i < 8; ++i) {
            float4 p = s_part[i][lane];
            r.x += p.x; r.y += p.y; r.z += p.z; r.w += p.w;
        }
        float* rec = g_part + ((size_t)(hop * BATCH + b) * SPLITS + split) * REC;
        reinterpret_cast<float4*>(rec + 4)[lane] = r;
        if (lane == 0) { rec[0] = s_ms[0]; rec[1] = s_ms[1]; }
    }
}

// ---------------------------------------------------------------------------
// Finalize: u_final = sum over hops of o_j / s_j. One warp per batch element.
// ---------------------------------------------------------------------------
__global__ void __launch_bounds__(32) finalize_kernel(float* __restrict__ out)
{
    const int b    = blockIdx.x;
    const int lane = threadIdx.x;

    float4 u4 = make_float4(0.f, 0.f, 0.f, 0.f);
    #pragma unroll
    for (int j = 0; j < HOPS; ++j) {
        float4 c = combine_hop(j, b, lane);
        u4.x += c.x; u4.y += c.y; u4.z += c.z; u4.w += c.w;
    }
    reinterpret_cast<float4*>(out + b * DIM)[lane] = u4;
}

// ---------------------------------------------------------------------------
extern "C" void kernel_launch(void* const* d_in, const int* in_sizes, int n_in,
                              void* d_out, int out_size)
{
    const float* C     = (const float*)d_in[0];  // [4, 50257, 128]
    const int*   story = (const int*)  d_in[1];  // [32, 512, 6]
    const int*   kb    = (const int*)  d_in[2];  // [32, 128, 64]
    float*       out   = (float*)d_out;          // [32, 128]

    const int total_warps = NTAB * BATCH * SLOTS;     // 81920
    gather_kernel<<<total_warps / 8, 256>>>(C, story, kb);

    for (int hop = 0; hop < HOPS; ++hop)
        hop_kernel<<<BATCH * SPLITS, 256>>>(hop);     // 640 blocks

    finalize_kernel<<<BATCH, 32>>>(out);
}

// round 3
// speedup vs baseline: 2.4431x; 1.1499x over previous
#include <cuda_runtime.h>
#include <cuda_bf16.h>

#define HOPS    3
#define VOCAB   50257
#define DIM     128
#define BATCH   32
#define M_SLOTS 512
#define S_TOK   6
#define T_TREE  128
#define L_TOK   64
#define SLOTS   (M_SLOTS + T_TREE)   // 640

#define NGTAB   3                    // tables 1..3 gathered (table 0 unused)
#define SPLITS   40                  // slot-splits per batch per hop
#define SLOTS_PB (SLOTS / SPLITS)    // 16 slots per block
#define REC      132                 // m, s, pad, pad, o[128]

// Scratch: g_M[t] holds table (t+1). 3*32*640*128 floats = 31.5 MB
__device__ float g_M[(size_t)NGTAB * BATCH * SLOTS * DIM];
__device__ __align__(16) float g_part[(size_t)2 * BATCH * SPLITS * REC];
__device__ __align__(16) float g_u[2 * BATCH * DIM];   // [0]=u1, [1]=u2

__device__ __forceinline__ float warp_max(float v) {
    #pragma unroll
    for (int o = 16; o; o >>= 1) v = fmaxf(v, __shfl_xor_sync(0xffffffffu, v, o));
    return v;
}
__device__ __forceinline__ float warp_sum(float v) {
    #pragma unroll
    for (int o = 16; o; o >>= 1) v += __shfl_xor_sync(0xffffffffu, v, o);
    return v;
}

// ---------------------------------------------------------------------------
// Phase 1: gather-sum tables 1..3. One warp per (t, b, slot).
// ---------------------------------------------------------------------------
__global__ void __launch_bounds__(256) gather_kernel(
    const float* __restrict__ C,
    const int*   __restrict__ story,
    const int*   __restrict__ kb)
{
    const int lane = threadIdx.x & 31;
    const int wg   = blockIdx.x * (blockDim.x >> 5) + (threadIdx.x >> 5);
    const int t    = wg / (BATCH * SLOTS);           // 0..2 -> table t+1
    const int rem  = wg % (BATCH * SLOTS);
    const int b    = rem / SLOTS;
    const int slot = rem % SLOTS;

    const float4* __restrict__ Ct =
        reinterpret_cast<const float4*>(C + (size_t)(t + 1) * VOCAB * DIM);

    float4 acc = make_float4(0.f, 0.f, 0.f, 0.f);

    if (slot < M_SLOTS) {
        const int* toks = story + ((size_t)b * M_SLOTS + slot) * S_TOK;
        int tk[S_TOK];
        #pragma unroll
        for (int j = 0; j < S_TOK; ++j) tk[j] = toks[j];
        #pragma unroll
        for (int j = 0; j < S_TOK; ++j) {
            float4 v = Ct[(size_t)tk[j] * (DIM / 4) + lane];
            acc.x += v.x; acc.y += v.y; acc.z += v.z; acc.w += v.w;
        }
    } else {
        const int* toks = kb + ((size_t)b * T_TREE + (slot - M_SLOTS)) * L_TOK;
        float4 a0 = make_float4(0.f, 0.f, 0.f, 0.f);
        float4 a1 = a0, a2 = a0, a3 = a0;
        #pragma unroll 4
        for (int j = 0; j < L_TOK; j += 4) {
            int t0 = toks[j + 0], t1 = toks[j + 1];
            int t2 = toks[j + 2], t3 = toks[j + 3];
            float4 v0 = Ct[(size_t)t0 * (DIM / 4) + lane];
            float4 v1 = Ct[(size_t)t1 * (DIM / 4) + lane];
            float4 v2 = Ct[(size_t)t2 * (DIM / 4) + lane];
            float4 v3 = Ct[(size_t)t3 * (DIM / 4) + lane];
            a0.x += v0.x; a0.y += v0.y; a0.z += v0.z; a0.w += v0.w;
            a1.x += v1.x; a1.y += v1.y; a1.z += v1.z; a1.w += v1.w;
            a2.x += v2.x; a2.y += v2.y; a2.z += v2.z; a2.w += v2.w;
            a3.x += v3.x; a3.y += v3.y; a3.z += v3.z; a3.w += v3.w;
        }
        acc.x = (a0.x + a1.x) + (a2.x + a3.x);
        acc.y = (a0.y + a1.y) + (a2.y + a3.y);
        acc.z = (a0.z + a1.z) + (a2.z + a3.z);
        acc.w = (a0.w + a1.w) + (a2.w + a3.w);
    }

    float4* out = reinterpret_cast<float4*>(g_M) + (size_t)wg * (DIM / 4);
    out[lane] = acc;
}

// ---------------------------------------------------------------------------
// u1 = (1/SLOTS) * sum over slots of M[table1].  (hop 0 with u=0 is uniform)
// One block per batch: 1024 threads = 8 slot-groups x 128 dims.
// ---------------------------------------------------------------------------
__global__ void __launch_bounds__(1024) u1_kernel()
{
    const int b = blockIdx.x;
    const int d = threadIdx.x & 127;
    const int g = threadIdx.x >> 7;          // 0..7, each sums 80 slots

    const float* __restrict__ base = g_M + ((size_t)b * SLOTS) * DIM;  // table1

    float acc = 0.f;
    #pragma unroll 8
    for (int s = g * 80; s < (g + 1) * 80; ++s)
        acc += base[(size_t)s * DIM + d];

    __shared__ float sm[1024];
    sm[threadIdx.x] = acc;
    __syncthreads();
    if (g == 0) {
        float tot = 0.f;
        #pragma unroll
        for (int i = 0; i < 8; ++i) tot += sm[i * 128 + d];
        g_u[b * DIM + d] = tot * (1.0f / SLOTS);
    }
}

// ---------------------------------------------------------------------------
// One hop, split over slots. Block = (b, split) handles 16 slots.
// kidx/vidx select key/value tensors inside g_M; uidx selects u in g_u.
// ---------------------------------------------------------------------------
__global__ void __launch_bounds__(256) hop_kernel(int kidx, int vidx,
                                                  int uidx, int pidx)
{
    const int b     = blockIdx.x / SPLITS;
    const int split = blockIdx.x % SPLITS;
    const int w     = threadIdx.x >> 5;
    const int lane  = threadIdx.x & 31;

    __shared__ float  s_score[SLOTS_PB];
    __shared__ float4 s_part[8][32];
    __shared__ float  s_ms[2];

    const float4 u4 =
        reinterpret_cast<const float4*>(g_u + (uidx * BATCH + b) * DIM)[lane];

    const float* __restrict__ Mk =
        g_M + ((size_t)(kidx * BATCH + b) * SLOTS + split * SLOTS_PB) * DIM;
    const float* __restrict__ Mv =
        g_M + ((size_t)(vidx * BATCH + b) * SLOTS + split * SLOTS_PB) * DIM;

    // --- scores: warp w handles local slots w and w+8 ---
    #pragma unroll
    for (int k = 0; k < SLOTS_PB / 8; ++k) {
        const int ls = w + k * 8;
        const float4 v = reinterpret_cast<const float4*>(Mk + (size_t)ls * DIM)[lane];
        float p = v.x * u4.x + v.y * u4.y + v.z * u4.z + v.w * u4.w;
        p = warp_sum(p);
        if (lane == 0) s_score[ls] = p;
    }
    __syncthreads();

    // --- local softmax over 16 scores (warp 0, lanes 0..15) ---
    if (w == 0) {
        float sc = (lane < SLOTS_PB) ? s_score[lane] : -1e30f;
        float m  = warp_max(sc);
        float e  = (lane < SLOTS_PB) ? __expf(sc - m) : 0.f;
        float s  = warp_sum(e);
        if (lane < SLOTS_PB) s_score[lane] = e;   // unnormalized
        if (lane == 0) { s_ms[0] = m; s_ms[1] = s; }
    }
    __syncthreads();

    // --- weighted value partial ---
    float4 o4 = make_float4(0.f, 0.f, 0.f, 0.f);
    #pragma unroll
    for (int k = 0; k < SLOTS_PB / 8; ++k) {
        const int ls = w + k * 8;
        const float  p = s_score[ls];
        const float4 v = reinterpret_cast<const float4*>(Mv + (size_t)ls * DIM)[lane];
        o4.x += p * v.x; o4.y += p * v.y; o4.z += p * v.z; o4.w += p * v.w;
    }
    s_part[w][lane] = o4;
    __syncthreads();

    if (w == 0) {
        float4 r = make_float4(0.f, 0.f, 0.f, 0.f);
        #pragma unroll
        for (int i = 0; i < 8; ++i) {
            float4 p = s_part[i][lane];
            r.x += p.x; r.y += p.y; r.z += p.z; r.w += p.w;
        }
        float* rec = g_part + ((size_t)(pidx * BATCH + b) * SPLITS + split) * REC;
        reinterpret_cast<float4*>(rec + 4)[lane] = r;
        if (lane == 0) { rec[0] = s_ms[0]; rec[1] = s_ms[1]; }
    }
}

// ---------------------------------------------------------------------------
// Combine split partials of hop pidx: dst = u_prev + o/s.  One warp per batch.
// ---------------------------------------------------------------------------
__global__ void __launch_bounds__(32) combine_kernel(int pidx, int u_src,
                                                     float* __restrict__ dst)
{
    const int b    = blockIdx.x;
    const int lane = threadIdx.x;

    const float* __restrict__ base =
        g_part + ((size_t)(pidx * BATCH + b)) * SPLITS * REC;

    float mi = base[lane * REC];                      // recs 0..31
    if (lane < SPLITS - 32)
        mi = fmaxf(mi, base[(lane + 32) * REC]);      // recs 32..39
    const float m = warp_max(mi);

    float s_acc = 0.f;
    float4 o4 = make_float4(0.f, 0.f, 0.f, 0.f);
    #pragma unroll
    for (int i = 0; i < SPLITS; ++i) {
        const float* rec = base + (size_t)i * REC;
        float e = __expf(rec[0] - m);
        s_acc += rec[1] * e;
        float4 oi = reinterpret_cast<const float4*>(rec + 4)[lane];
        o4.x += e * oi.x; o4.y += e * oi.y; o4.z += e * oi.z; o4.w += e * oi.w;
    }
    const float inv = 1.0f / s_acc;

    const float4 u4 =
        reinterpret_cast<const float4*>(g_u + (u_src * BATCH + b) * DIM)[lane];
    float4 r;
    r.x = u4.x + o4.x * inv;
    r.y = u4.y + o4.y * inv;
    r.z = u4.z + o4.z * inv;
    r.w = u4.w + o4.w * inv;
    reinterpret_cast<float4*>(dst + b * DIM)[lane] = r;
}

// ---------------------------------------------------------------------------
extern "C" void kernel_launch(void* const* d_in, const int* in_sizes, int n_in,
                              void* d_out, int out_size)
{
    const float* C     = (const float*)d_in[0];  // [4, 50257, 128]
    const int*   story = (const int*)  d_in[1];  // [32, 512, 6]
    const int*   kb    = (const int*)  d_in[2];  // [32, 128, 64]
    float*       out   = (float*)d_out;          // [32, 128]

    float* u2;
    cudaGetSymbolAddress((void**)&u2, g_u);      // host-side, capture-safe
    u2 += BATCH * DIM;

    const int total_warps = NGTAB * BATCH * SLOTS;          // 61440
    gather_kernel<<<total_warps / 8, 256>>>(C, story, kb);  // tables 1..3

    u1_kernel<<<BATCH, 1024>>>();                            // u1 (hop 0)

    hop_kernel<<<BATCH * SPLITS, 256>>>(0, 1, 0, 0);         // hop 1: M1 key, M2 val
    combine_kernel<<<BATCH, 32>>>(0, 0, u2);                 // u2 = u1 + o1

    hop_kernel<<<BATCH * SPLITS, 256>>>(1, 2, 1, 1);         // hop 2: M2 key, M3 val
    combine_kernel<<<BATCH, 32>>>(1, 1, out);                // out = u2 + o2
}